// round 1
// baseline (speedup 1.0000x reference)
#include <cuda_runtime.h>

#define LSEQ 512
#define BSZ 1024
#define NTAG 64
#define START_TAG 62
#define END_TAG 63

// ---- packed f32x2 helpers (Blackwell FFMA2 path: only reachable via PTX) ----
__device__ __forceinline__ unsigned long long pack2(float lo, float hi) {
    unsigned long long d;
    asm("mov.b64 %0, {%1, %2};" : "=l"(d) : "f"(lo), "f"(hi));
    return d;
}
__device__ __forceinline__ void unpack2(unsigned long long v, float& lo, float& hi) {
    asm("mov.b64 {%0, %1}, %2;" : "=f"(lo), "=f"(hi) : "l"(v));
}
__device__ __forceinline__ unsigned long long fma2(unsigned long long a,
                                                   unsigned long long b,
                                                   unsigned long long c) {
    unsigned long long d;
    asm("fma.rn.f32x2 %0, %1, %2, %3;" : "=l"(d) : "l"(a), "l"(b), "l"(c));
    return d;
}
__device__ __forceinline__ unsigned long long add2(unsigned long long a,
                                                   unsigned long long b) {
    unsigned long long d;
    asm("add.rn.f32x2 %0, %1, %2;" : "=l"(d) : "l"(a), "l"(b));
    return d;
}
__device__ __forceinline__ unsigned long long mul2(unsigned long long a,
                                                   unsigned long long b) {
    unsigned long long d;
    asm("mul.rn.f32x2 %0, %1, %2;" : "=l"(d) : "l"(a), "l"(b));
    return d;
}

// ============================================================================
// Forward (all-path) kernel. One warp per batch element.
// Lane owns tags (2*lane, 2*lane+1). E2 rows live in 128 registers per thread.
// v kept linear-domain, duplicated (v,v) in shared so LDS.128 feeds f32x2 FMA
// directly via warp-uniform broadcast loads. Renorm every 4 steps.
// ============================================================================
__global__ __launch_bounds__(128, 1) void crf_forward_kernel(
    const float* __restrict__ feats,
    const float* __restrict__ mask,
    const float* __restrict__ transition,
    float* __restrict__ out)
{
    __shared__ __align__(16) float2 vsh[4][NTAG];
    const int warp = threadIdx.x >> 5;
    const int lane = threadIdx.x & 31;
    const int b = blockIdx.x * 4 + warp;
    float2* vdup = vsh[warp];
    const int t0 = lane * 2;
    const int t1 = t0 + 1;

    // E2[p] = ( exp(transition[t0][p]), exp(transition[t1][p]) )  -- constant.
    unsigned long long e2[NTAG];
#pragma unroll
    for (int p = 0; p < NTAG; ++p) {
        float lo = __expf(__ldg(transition + t0 * NTAG + p));
        float hi = __expf(__ldg(transition + t1 * NTAG + p));
        e2[p] = pack2(lo, hi);
    }

    // alpha0 = NEG everywhere except START=0  ->  v = one-hot(START), c = 0
    {
        float v0 = (t0 == START_TAG) ? 1.0f : 0.0f;
        float v1 = (t1 == START_TAG) ? 1.0f : 0.0f;
        *(float4*)&vdup[t0] = make_float4(v0, v0, v1, v1);
    }
    float c = 0.0f;
    __syncwarp();

    const float* fptr = feats + (size_t)b * NTAG + t0;
    float2 fnext = *(const float2*)fptr;              // step 0 prefetch
    float  mnext = __ldg(mask + b);

    for (int l = 0; l < LSEQ; ++l) {
        const float2 f = fnext;
        const float  m = mnext;
        const int ln = (l + 1 < LSEQ) ? (l + 1) : (LSEQ - 1);
        fnext = *(const float2*)(fptr + (size_t)ln * (BSZ * NTAG));
        mnext = __ldg(mask + ln * BSZ + b);

        // v' = E @ v   (4 independent f32x2 accumulator chains)
        unsigned long long a0 = 0ull, a1 = 0ull, a2 = 0ull, a3 = 0ull;
        const ulonglong2* v2p = (const ulonglong2*)vdup;
#pragma unroll
        for (int i = 0; i < 32; i += 2) {
            ulonglong2 w0 = v2p[i];       // ((v[2i],v[2i]),(v[2i+1],v[2i+1]))
            ulonglong2 w1 = v2p[i + 1];
            a0 = fma2(e2[2 * i + 0], w0.x, a0);
            a1 = fma2(e2[2 * i + 1], w0.y, a1);
            a2 = fma2(e2[2 * i + 2], w1.x, a2);
            a3 = fma2(e2[2 * i + 3], w1.y, a3);
        }
        __syncwarp();   // all reads of vdup done before anyone overwrites

        unsigned long long s2 = add2(add2(a0, a1), add2(a2, a3));
        unsigned long long ef = pack2(__expf(f.x), __expf(f.y));
        unsigned long long vp = mul2(s2, ef);

        if (m != 0.0f) {   // warp-uniform (mask is per (l,b)); select semantics
            float v0, v1;
            unpack2(vp, v0, v1);
            if ((l & 3) == 3) {   // renorm every 4 steps (growth <= ~1.6e23)
                float hi = fmaxf(v0, v1);
#pragma unroll
                for (int o = 16; o > 0; o >>= 1)
                    hi = fmaxf(hi, __shfl_xor_sync(0xffffffffu, hi, o));
                float inv = __fdividef(1.0f, hi);
                c += __logf(hi);
                v0 *= inv;
                v1 *= inv;
            }
            *(float4*)&vdup[t0] = make_float4(v0, v0, v1, v1);  // conflict-free STS.128
        }
        __syncwarp();
    }

    // allpath = c + log( sum_t v[t] * exp(transition[END][t]) )
    float v0 = vdup[t0].x;
    float v1 = vdup[t1].x;
    float s = v0 * __expf(__ldg(transition + END_TAG * NTAG + t0))
            + v1 * __expf(__ldg(transition + END_TAG * NTAG + t1));
#pragma unroll
    for (int o = 16; o > 0; o >>= 1)
        s += __shfl_xor_sync(0xffffffffu, s, o);
    if (lane == 0) out[b] = c + __logf(s);
}

// ============================================================================
// Real-path (gold sequence) score; subtracts from out written by forward.
// Block = 256 threads handles 32 batches; lanes = batches (coalesced tag/mask
// loads), 8 warps split the L dimension, reduce in shared.
// ============================================================================
__global__ __launch_bounds__(256, 1) void crf_realpath_kernel(
    const float* __restrict__ feats,
    const int*   __restrict__ tags,
    const float* __restrict__ mask,
    const float* __restrict__ transition,
    float* __restrict__ out)
{
    const int lane = threadIdx.x & 31;
    const int warp = threadIdx.x >> 5;
    const int b = blockIdx.x * 32 + lane;

    __shared__ float s_sum[8][32];
    __shared__ float s_len[8][32];

    float s = 0.0f, len = 0.0f;
    for (int l = warp; l < LSEQ; l += 8) {
        int tag  = __ldg(tags + l * BSZ + b);
        int prev = (l == 0) ? START_TAG : __ldg(tags + (l - 1) * BSZ + b);
        float m  = __ldg(mask + l * BSZ + b);
        float emit = __ldg(feats + ((size_t)l * BSZ + b) * NTAG + tag);
        float tr   = __ldg(transition + tag * NTAG + prev);
        s   += (emit + tr) * m;
        len += m;
    }
    s_sum[warp][lane] = s;
    s_len[warp][lane] = len;
    __syncthreads();

    if (warp == 0) {
        float st = 0.0f, lt = 0.0f;
#pragma unroll
        for (int w = 0; w < 8; ++w) { st += s_sum[w][lane]; lt += s_len[w][lane]; }
        int length = (int)(lt + 0.5f);
        int last = (length > 0) ? __ldg(tags + (length - 1) * BSZ + b) : START_TAG;
        float real = st + __ldg(transition + END_TAG * NTAG + last);
        out[b] = out[b] - real;
    }
}

extern "C" void kernel_launch(void* const* d_in, const int* in_sizes, int n_in,
                              void* d_out, int out_size) {
    const float* feats      = (const float*)d_in[0];
    const int*   tags       = (const int*)  d_in[1];
    const float* mask       = (const float*)d_in[2];
    const float* transition = (const float*)d_in[3];
    float* out = (float*)d_out;

    crf_forward_kernel<<<BSZ / 4, 128>>>(feats, mask, transition, out);
    crf_realpath_kernel<<<BSZ / 32, 256>>>(feats, tags, mask, transition, out);
}

// round 2
// speedup vs baseline: 1.4189x; 1.4189x over previous
#include <cuda_runtime.h>

#define LSEQ 512
#define BSZ 1024
#define NTAG 64
#define START_TAG 62
#define END_TAG 63

typedef unsigned long long ull;

// ---- packed f32x2 helpers (Blackwell FFMA2: only reachable via PTX) ----
__device__ __forceinline__ ull pack2(float lo, float hi) {
    ull d;
    asm("mov.b64 %0, {%1, %2};" : "=l"(d) : "f"(lo), "f"(hi));
    return d;
}
__device__ __forceinline__ void unpack2(ull v, float& lo, float& hi) {
    asm("mov.b64 {%0, %1}, %2;" : "=f"(lo), "=f"(hi) : "l"(v));
}
__device__ __forceinline__ ull fma2(ull a, ull b, ull c) {
    ull d;
    asm("fma.rn.f32x2 %0, %1, %2, %3;" : "=l"(d) : "l"(a), "l"(b), "l"(c));
    return d;
}
__device__ __forceinline__ ull add2(ull a, ull b) {
    ull d;
    asm("add.rn.f32x2 %0, %1, %2;" : "=l"(d) : "l"(a), "l"(b));
    return d;
}

// ============================================================================
// Fused CRF kernel. One warp per batch element, 4 warps per block.
//
// Forward recurrence in the linear domain: v' = (E @ v) * exp(feat), with a
// running log-scale c renormalized every 4 steps. Lane owns output tags
// (2*lane, 2*lane+1). f32x2 packing: .lo accumulates even source tags,
// .hi odd source tags, so the shared-memory operand is the natural pair
// (v[2i], v[2i+1]) -> unduplicated v, 16 LDS.128 + 64 FFMA2 per step.
// Ping-pong v buffers -> single __syncwarp per step. feats prefetched 4
// steps ahead in a register ring. Realpath (gold score) computed as a
// per-warp tail with lanes split over L for full MLP.
// ============================================================================
__global__ __launch_bounds__(128) void crf_fused_kernel(
    const float* __restrict__ feats,
    const int*   __restrict__ tags,
    const float* __restrict__ mask,
    const float* __restrict__ transition,
    float* __restrict__ out)
{
    __shared__ __align__(16) float vsh[2][4][NTAG];
    const int warp = threadIdx.x >> 5;
    const int lane = threadIdx.x & 31;
    const int b = blockIdx.x * 4 + warp;
    const int t0 = 2 * lane;
    const int t1 = t0 + 1;

    // e0[i] = (E[t0,2i], E[t0,2i+1]),  e1[i] = (E[t1,2i], E[t1,2i+1])
    ull e0[32], e1[32];
#pragma unroll
    for (int i = 0; i < 32; ++i) {
        e0[i] = pack2(__expf(__ldg(transition + t0 * NTAG + 2 * i)),
                      __expf(__ldg(transition + t0 * NTAG + 2 * i + 1)));
        e1[i] = pack2(__expf(__ldg(transition + t1 * NTAG + 2 * i)),
                      __expf(__ldg(transition + t1 * NTAG + 2 * i + 1)));
    }

    // alpha0 = NEG except START=0  ->  v = one-hot(START), c = 0
    float myv0 = (t0 == START_TAG) ? 1.0f : 0.0f;
    float myv1 = (t1 == START_TAG) ? 1.0f : 0.0f;
    ((float2*)vsh[0][warp])[lane] = make_float2(myv0, myv1);
    float c = 0.0f;
    __syncwarp();

    // 4-deep prefetch ring for feats/mask
    const float* fptr = feats + (size_t)b * NTAG + t0;
    float2 fr[4];
    float  mr[4];
#pragma unroll
    for (int u = 0; u < 4; ++u) {
        fr[u] = *(const float2*)(fptr + (size_t)u * (BSZ * NTAG));
        mr[u] = __ldg(mask + u * BSZ + b);
    }

    for (int l4 = 0; l4 < LSEQ; l4 += 4) {
#pragma unroll
        for (int u = 0; u < 4; ++u) {
            const int l = l4 + u;
            const float2 f = fr[u];
            const float  m = mr[u];
            int ln = l + 4;
            if (ln > LSEQ - 1) ln = LSEQ - 1;
            fr[u] = *(const float2*)(fptr + (size_t)ln * (BSZ * NTAG));
            mr[u] = __ldg(mask + ln * BSZ + b);

            // v' = E @ v : 4 independent f32x2 chains, broadcast LDS.128
            const ulonglong2* vp = (const ulonglong2*)vsh[l & 1][warp];
            ull ae0 = 0ull, ae1 = 0ull, ao0 = 0ull, ao1 = 0ull;
#pragma unroll
            for (int i = 0; i < 16; ++i) {
                ulonglong2 w = vp[i];   // ((v[4i],v[4i+1]),(v[4i+2],v[4i+3]))
                ae0 = fma2(e0[2 * i],     w.x, ae0);
                ae1 = fma2(e1[2 * i],     w.x, ae1);
                ao0 = fma2(e0[2 * i + 1], w.y, ao0);
                ao1 = fma2(e1[2 * i + 1], w.y, ao1);
            }
            ull s0 = add2(ae0, ao0);
            ull s1 = add2(ae1, ao1);
            float s0l, s0h, s1l, s1h;
            unpack2(s0, s0l, s0h);
            unpack2(s1, s1l, s1h);
            float v0n = (s0l + s0h) * __expf(f.x);
            float v1n = (s1l + s1h) * __expf(f.y);

            if (m == 0.0f) { v0n = myv0; v1n = myv1; }  // warp-uniform mask

            if ((l & 3) == 3) {   // unconditional renorm every 4 steps
                float hi = fmaxf(v0n, v1n);
#pragma unroll
                for (int o = 16; o > 0; o >>= 1)
                    hi = fmaxf(hi, __shfl_xor_sync(0xffffffffu, hi, o));
                c += __logf(hi);
                float inv = __fdividef(1.0f, hi);
                v0n *= inv;
                v1n *= inv;
            }
            myv0 = v0n;
            myv1 = v1n;
            ((float2*)vsh[(l & 1) ^ 1][warp])[lane] = make_float2(v0n, v1n);
            __syncwarp();
        }
    }

    // allpath = c + log( sum_t v[t] * exp(transition[END][t]) )
    float s = myv0 * __expf(__ldg(transition + END_TAG * NTAG + t0))
            + myv1 * __expf(__ldg(transition + END_TAG * NTAG + t1));
#pragma unroll
    for (int o = 16; o > 0; o >>= 1)
        s += __shfl_xor_sync(0xffffffffu, s, o);
    const float allpath = c + __logf(s);

    // ---- realpath tail: lanes split L (16 each), independent gathers ----
    float rsum = 0.0f, rlen = 0.0f;
#pragma unroll
    for (int i = 0; i < 16; ++i) {
        const int l = lane + 32 * i;
        int tag  = __ldg(tags + l * BSZ + b);
        int prev = (l == 0) ? START_TAG : __ldg(tags + (l - 1) * BSZ + b);
        float m  = __ldg(mask + l * BSZ + b);
        float emit = __ldg(feats + ((size_t)l * BSZ + b) * NTAG + tag);
        float tr   = __ldg(transition + tag * NTAG + prev);
        rsum += (emit + tr) * m;
        rlen += m;
    }
#pragma unroll
    for (int o = 16; o > 0; o >>= 1) {
        rsum += __shfl_xor_sync(0xffffffffu, rsum, o);
        rlen += __shfl_xor_sync(0xffffffffu, rlen, o);
    }
    if (lane == 0) {
        int length = (int)(rlen + 0.5f);
        int last = (length > 0) ? __ldg(tags + (length - 1) * BSZ + b) : START_TAG;
        float real = rsum + __ldg(transition + END_TAG * NTAG + last);
        out[b] = allpath - real;
    }
}

extern "C" void kernel_launch(void* const* d_in, const int* in_sizes, int n_in,
                              void* d_out, int out_size) {
    const float* feats      = (const float*)d_in[0];
    const int*   tags       = (const int*)  d_in[1];
    const float* mask       = (const float*)d_in[2];
    const float* transition = (const float*)d_in[3];
    float* out = (float*)d_out;

    crf_fused_kernel<<<BSZ / 4, 128>>>(feats, tags, mask, transition, out);
}